// round 16
// baseline (speedup 1.0000x reference)
#include <cuda_runtime.h>
#include <cuda_bf16.h>
#include <cstdint>
#include <math.h>

// ---------------------------------------------------------------------------
// GraphSageWithSampling — warp-mma bf16 split-precision, round 16
// = round 15 (988us, best) + NARROW BARRIERS ported to the conv kernels
//   (the round-9 node transformation, ownership re-proved for conv):
//  * A-tile rows rg-private (warp pair): split/gather writes + GEMM A-reads
//    all within rows 32k..32k+32 -> 64-thr rg-bars.
//  * B-tile feature rows cg-private ((warp&1) half): weight loads cg-scoped
//    (128-thr) + 128-thr cg-bars.
//  * BLK==2 L2-reduce spans only the rg pair -> rg-bar.
// Node kernel: byte-identical to round 15 (protected win).
// Numerics bit-identical; rel_err canary 1.058542e-5.
// ---------------------------------------------------------------------------

namespace {
constexpr int L0 = 524288, L1 = 131072, L2 = 32768, L3 = 8192;
}

// scratch activations
__device__ float g_h0[(long long)L0 * 128];
__device__ float g_h1[(long long)L1 * 128];
__device__ float g_h2[(long long)L2 * 128];
__device__ float g_h3[(long long)L3 * 128];

// pre-split, pre-transposed weights: [F=128][K] row-major, hi/lo bf16
__device__ __nv_bfloat16 g_wexp_hi[128 * 32],  g_wexp_lo[128 * 32];
__device__ __nv_bfloat16 g_wproj_hi[128 * 32], g_wproj_lo[128 * 32];
__device__ __nv_bfloat16 g_wd1_hi[128 * 128],  g_wd1_lo[128 * 128];
__device__ __nv_bfloat16 g_wd2_hi[128 * 128],  g_wd2_lo[128 * 128];
__device__ __nv_bfloat16 g_wc1_hi[3 * 128 * 256], g_wc1_lo[3 * 128 * 256];
__device__ __nv_bfloat16 g_wc2_hi[3 * 128 * 128], g_wc2_lo[3 * 128 * 128];

__device__ __forceinline__ uint32_t smem_u32(const void* p) {
    uint32_t a;
    asm("{ .reg .u64 t; cvta.to.shared.u64 t, %1; cvt.u32.u64 %0, t; }" : "=r"(a) : "l"(p));
    return a;
}
__device__ __forceinline__ float lrelu(float x, float s) { return x >= 0.0f ? x : x * s; }

__device__ __forceinline__ void bar_sync(int id, int cnt) {
    asm volatile("bar.sync %0, %1;" :: "r"(id), "r"(cnt) : "memory");
}

__device__ __forceinline__ void ldsm4(unsigned (&r)[4], uint32_t a) {
    asm volatile("ldmatrix.sync.aligned.m8n8.x4.shared.b16 {%0,%1,%2,%3}, [%4];"
                 : "=r"(r[0]), "=r"(r[1]), "=r"(r[2]), "=r"(r[3]) : "r"(a));
}
__device__ __forceinline__ void mma_bf16(float (&c)[4], const unsigned (&a)[4],
                                         unsigned b0, unsigned b1) {
    asm("mma.sync.aligned.m16n8k16.row.col.f32.bf16.bf16.f32 "
        "{%0,%1,%2,%3}, {%4,%5,%6,%7}, {%8,%9}, {%0,%1,%2,%3};"
        : "+f"(c[0]), "+f"(c[1]), "+f"(c[2]), "+f"(c[3])
        : "r"(a[0]), "r"(a[1]), "r"(a[2]), "r"(a[3]), "r"(b0), "r"(b1));
}
__device__ __forceinline__ void cp16(uint32_t saddr, const void* g) {
    asm volatile("cp.async.cg.shared.global [%0], [%1], 16;" :: "r"(saddr), "l"(g));
}
#define CP_COMMIT() asm volatile("cp.async.commit_group;" ::: "memory")
#define CP_WAIT0()  asm volatile("cp.async.wait_group 0;" ::: "memory")
#define CP_WAIT1()  asm volatile("cp.async.wait_group 1;" ::: "memory")

__device__ __forceinline__ void zeroC2(float (&C)[2][8][4]) {
#pragma unroll
    for (int m = 0; m < 2; m++)
#pragma unroll
        for (int i = 0; i < 8; i++)
#pragma unroll
            for (int j = 0; j < 4; j++) C[m][i][j] = 0.0f;
}

// split fp32 pair -> hi/lo bf16 pairs (u32 each) into strided tiles
__device__ __forceinline__ void split_pair(char* hi, char* lo, int stride,
                                           int row, int col, float x0, float x1) {
    __nv_bfloat16 h0 = __float2bfloat16(x0), h1 = __float2bfloat16(x1);
    __nv_bfloat16 l0 = __float2bfloat16(x0 - __bfloat162float(h0));
    __nv_bfloat16 l1 = __float2bfloat16(x1 - __bfloat162float(h1));
    int off = (row * stride + col) * 2;
    *(uint32_t*)(hi + off) = (uint32_t)__bfloat16_as_ushort(h0) |
                             ((uint32_t)__bfloat16_as_ushort(h1) << 16);
    *(uint32_t*)(lo + off) = (uint32_t)__bfloat16_as_ushort(l0) |
                             ((uint32_t)__bfloat16_as_ushort(l1) << 16);
}

// split fp32 quad -> hi/lo bf16, single uint2 (STS.64) per tile.
__device__ __forceinline__ void split_quad(char* hi, char* lo, int stride,
                                           int row, int col, float4 q) {
    __nv_bfloat16 h0 = __float2bfloat16(q.x), h1 = __float2bfloat16(q.y);
    __nv_bfloat16 h2 = __float2bfloat16(q.z), h3 = __float2bfloat16(q.w);
    __nv_bfloat16 l0 = __float2bfloat16(q.x - __bfloat162float(h0));
    __nv_bfloat16 l1 = __float2bfloat16(q.y - __bfloat162float(h1));
    __nv_bfloat16 l2 = __float2bfloat16(q.z - __bfloat162float(h2));
    __nv_bfloat16 l3 = __float2bfloat16(q.w - __bfloat162float(h3));
    int off = (row * stride + col) * 2;
    uint2 hv, lv;
    hv.x = (uint32_t)__bfloat16_as_ushort(h0) | ((uint32_t)__bfloat16_as_ushort(h1) << 16);
    hv.y = (uint32_t)__bfloat16_as_ushort(h2) | ((uint32_t)__bfloat16_as_ushort(h3) << 16);
    lv.x = (uint32_t)__bfloat16_as_ushort(l0) | ((uint32_t)__bfloat16_as_ushort(l1) << 16);
    lv.y = (uint32_t)__bfloat16_as_ushort(l2) | ((uint32_t)__bfloat16_as_ushort(l3) << 16);
    *(uint2*)(hi + off) = hv;
    *(uint2*)(lo + off) = lv;
}

// cg-scoped cp.async copy (256-thread cg, node kernel): cg's 64 feature rows
__device__ __forceinline__ void load_bt_cg(char* dst, const __nv_bfloat16* __restrict__ g,
                                           int gStride, int gcol0, int ncols, int dcol0,
                                           int ctid, int rowbase) {
    const int vec = ncols >> 3;
    const uint32_t db = smem_u32(dst);
    for (int i = ctid; i < 64 * vec; i += 256) {
        int r = i / vec, j = (i - r * vec) * 8;
        int f = rowbase + r;
        cp16(db + (uint32_t)(f * 136 + dcol0 + j) * 2, g + (size_t)f * gStride + gcol0 + j);
    }
}

// cg-scoped cp.async copy (128-thread cg, conv kernel): cg's 64 feature rows
__device__ __forceinline__ void load_bt_cg128(char* dst, const __nv_bfloat16* __restrict__ g,
                                              int gStride, int gcol0, int ncols,
                                              int ctid, int rowbase) {
    const int vec = ncols >> 3;
    const uint32_t db = smem_u32(dst);
    for (int i = ctid; i < 64 * vec; i += 128) {
        int r = i / vec, j = (i - r * vec) * 8;
        int f = rowbase + r;
        cp16(db + (uint32_t)(f * 136 + j) * 2, g + (size_t)f * gStride + gcol0 + j);
    }
}

// warp GEMM, 32x64 tile: C[2 m-tiles][8 n8][4] += 3-way split product.
template <int SA>
__device__ __forceinline__ void warp_gemm2(float (&C)[2][8][4],
                                           const char* aHi, const char* aLo,
                                           const char* bHi, const char* bLo,
                                           int wrow0, int bcol0, int aCol0, int bCol0,
                                           int nkb, int lane)
{
    const int lr = lane & 7, quad = lane >> 3;
    const uint32_t aBH = smem_u32(aHi), aBL = smem_u32(aLo);
    const uint32_t bBH = smem_u32(bHi), bBL = smem_u32(bLo);
    const uint32_t aR0 =
        (uint32_t)(((wrow0 + ((quad & 1) << 3) + lr) * SA) + ((quad >> 1) << 3) + aCol0) * 2;
    const uint32_t aR1 = aR0 + (uint32_t)(16 * SA * 2);
    const int bRow = bcol0 + ((quad >> 1) << 3) + lr;
    const int bCol = ((quad & 1) << 3) + bCol0;
#pragma unroll 1
    for (int kb = 0; kb < nkb; kb++) {
        unsigned ah[2][4], al[2][4];
        uint32_t ak = (uint32_t)(kb * 32);
        ldsm4(ah[0], aBH + aR0 + ak);
        ldsm4(al[0], aBL + aR0 + ak);
        ldsm4(ah[1], aBH + aR1 + ak);
        ldsm4(al[1], aBL + aR1 + ak);
        unsigned bh[2][4], bl[2][4];
        uint32_t bo0 = (uint32_t)((bRow * 136) + bCol + kb * 16) * 2;
        ldsm4(bh[0], bBH + bo0);
        ldsm4(bl[0], bBL + bo0);
#pragma unroll
        for (int ntp = 0; ntp < 4; ntp++) {
            const int cur = ntp & 1, nxt = cur ^ 1;
            if (ntp < 3) {
                uint32_t bo = bo0 + (uint32_t)((ntp + 1) * 16 * 136) * 2;
                ldsm4(bh[nxt], bBH + bo);
                ldsm4(bl[nxt], bBL + bo);
            }
#pragma unroll
            for (int p = 0; p < 3; p++) {
#pragma unroll
                for (int m = 0; m < 2; m++) {
                    const unsigned (&A)[4] = (p == 1) ? al[m] : ah[m];
                    const unsigned*  B     = (p == 2) ? bl[cur] : bh[cur];
                    mma_bf16(C[m][2 * ntp],     A, B[0], B[1]);
                    mma_bf16(C[m][2 * ntp + 1], A, B[2], B[3]);
                }
            }
        }
    }
}

// ---------------------------------------------------------------------------
// prep kernel (unchanged, validated)
// ---------------------------------------------------------------------------
__global__ void prep_weights(const float* __restrict__ expW, const float* __restrict__ projW,
                             const float* __restrict__ dW1, const float* __restrict__ dW2,
                             const float* __restrict__ cW1, const float* __restrict__ cW2)
{
    int i = blockIdx.x * blockDim.x + threadIdx.x;
    float val; __nv_bfloat16 *dh, *dl; int di;
    if (i < 4096)        { int f = i >> 5,  k = i & 31;  val = expW[k * 128 + f];  dh = g_wexp_hi;  dl = g_wexp_lo;  di = i; }
    else if (i < 8192)   { int j = i - 4096;  int f = j >> 5,  k = j & 31;  val = projW[k * 128 + f]; dh = g_wproj_hi; dl = g_wproj_lo; di = j; }
    else if (i < 24576)  { int j = i - 8192;  int f = j >> 7,  k = j & 127; val = dW1[k * 128 + f];  dh = g_wd1_hi;  dl = g_wd1_lo;  di = j; }
    else if (i < 40960)  { int j = i - 24576; int f = j >> 7,  k = j & 127; val = dW2[k * 128 + f];  dh = g_wd2_hi;  dl = g_wd2_lo;  di = j; }
    else if (i < 139264) { int j = i - 40960; int b = j >> 15; int r = j & 32767; int f = r >> 8, k = r & 255;
                           val = cW1[(size_t)b * 32768 + k * 128 + f]; dh = g_wc1_hi; dl = g_wc1_lo; di = j; }
    else if (i < 188416) { int j = i - 139264; int b = j / 16384; int r = j - b * 16384; int f = r >> 7, k = r & 127;
                           val = cW2[(size_t)b * 16384 + k * 128 + f]; dh = g_wc2_hi; dl = g_wc2_lo; di = j; }
    else return;
    __nv_bfloat16 h = __float2bfloat16(val);
    dh[di] = h;
    dl[di] = __float2bfloat16(val - __bfloat162float(h));
}

namespace {
constexpr int BT  = 34816;                          // B tile 128x136 bf16
constexpr int ATn = 69632;                          // node A tile 256x136 bf16
constexpr int NODE_SMEM = 2 * ATn + 2 * BT + 1024;  // 209,920 B
constexpr int ATC = 67584;                          // conv A tile 128x264 bf16
constexpr int CONV_SMEM = 2 * ATC + 2 * BT + 1024;  // 205,824 B
constexpr int NB0 = 2048, NB1 = 512, NB2 = 128, NB3 = 32;    // 256-row blocks
constexpr int NODE_BLOCKS = NB0 + NB1 + NB2 + NB3;           // 2720
}

struct NodeArgs {
    const int *nid0, *nid1, *nid2, *nid3;
    const int *cat0, *cat1, *cat2, *cat3;
    const float *feat0, *feat1, *feat2, *feat3;
};

// ---------------------------------------------------------------------------
// Merged node transform kernel (UNCHANGED round-14/15 winning config).
// ---------------------------------------------------------------------------
__global__ void __launch_bounds__(512, 1)
node_kernel(NodeArgs A_,
            const float* __restrict__ node_emb,
            const float* __restrict__ expb, const float* __restrict__ emb_cat,
            const float* __restrict__ projb, const float* __restrict__ db1,
            const float* __restrict__ db2)
{
    extern __shared__ char sm[];
    char* aHi = sm;
    char* aLo = aHi + ATn;
    char* bHi = aLo + ATn;
    char* bLo = bHi + BT;
    int* s_cat = (int*)(bLo + BT);

    const int b = blockIdx.x;
    const int*   nid;  const int* cat;  const float* feat;  float* out;  size_t base;
    if (b < NB0)              { nid = A_.nid0; cat = A_.cat0; feat = A_.feat0; out = g_h0; base = (size_t)b * 256; }
    else if (b < NB0 + NB1)   { nid = A_.nid1; cat = A_.cat1; feat = A_.feat1; out = g_h1; base = (size_t)(b - NB0) * 256; }
    else if (b < NB0 + NB1 + NB2) { nid = A_.nid2; cat = A_.cat2; feat = A_.feat2; out = g_h2; base = (size_t)(b - NB0 - NB1) * 256; }
    else                      { nid = A_.nid3; cat = A_.cat3; feat = A_.feat3; out = g_h3; base = (size_t)(b - NB0 - NB1 - NB2) * 256; }

    const int tid = threadIdx.x, lane = tid & 31, warp = tid >> 5;
    const int wrow0 = (warp >> 1) * 32, bcol0 = (warp & 1) * 64;
    const int cgid  = warp & 1;
    const int ctid  = ((warp >> 1) << 5) + lane;
    const int rowb  = cgid * 64;
    const int CGB   = 1 + cgid;
    const int RGB   = 3 + (warp >> 1);

    if (tid < 256) s_cat[tid] = cat[base + tid];

    load_bt_cg(bHi, g_wexp_hi, 32, 0, 32, 0, ctid, rowb);
    load_bt_cg(bLo, g_wexp_lo, 32, 0, 32, 0, ctid, rowb);
    load_bt_cg(bHi, g_wproj_hi, 32, 0, 32, 32, ctid, rowb);
    load_bt_cg(bLo, g_wproj_lo, 32, 0, 32, 32, ctid, rowb);
    load_bt_cg(bHi, g_wd1_hi, 128, 0, 64, 64, ctid, rowb);
    load_bt_cg(bLo, g_wd1_lo, 128, 0, 64, 64, ctid, rowb);
    CP_COMMIT();

    // inputs: 8 LDG.128 batched (MLP 8), STS.64 stores
    {
        int row = tid >> 1, half = tid & 1;
        const float4* e4 = (const float4*)(node_emb + (size_t)(nid[base + row] + 1) * 32 + half * 16);
        const float4* f4 = (const float4*)(feat + (base + row) * 32 + half * 16);
        float4 qe[4], qf[4];
#pragma unroll
        for (int j = 0; j < 4; j++) qe[j] = e4[j];
#pragma unroll
        for (int j = 0; j < 4; j++) qf[j] = f4[j];
#pragma unroll
        for (int j = 0; j < 4; j++)
            split_quad(aHi, aLo, 136, row, half * 16 + 4 * j, qe[j]);
#pragma unroll
        for (int j = 0; j < 4; j++)
            split_quad(aHi, aLo, 136, row, 32 + half * 16 + 4 * j, qf[j]);
    }
    CP_WAIT0();
    __syncthreads();

    const int g = lane >> 2, t = lane & 3;
    float C[2][8][4];

    // G1
    zeroC2(C);
    warp_gemm2<136>(C, aHi, aLo, bHi, bLo, wrow0, bcol0, 0, 0, 2, lane);
#pragma unroll
    for (int m = 0; m < 2; m++) {
        float* oA = out + (base + wrow0 + m * 16 + g) * 128;
        float* oB = oA + 8 * 128;
#pragma unroll
        for (int nt = 0; nt < 8; nt++) {
            int col = bcol0 + nt * 8 + 2 * t;
            float2 bb = *(const float2*)(expb + col);
            *(float2*)(oA + col) = make_float2(lrelu(C[m][nt][0] + bb.x, 0.1f),
                                               lrelu(C[m][nt][1] + bb.y, 0.1f));
            *(float2*)(oB + col) = make_float2(lrelu(C[m][nt][2] + bb.x, 0.1f),
                                               lrelu(C[m][nt][3] + bb.y, 0.1f));
        }
    }

    // G2
    zeroC2(C);
    warp_gemm2<136>(C, aHi, aLo, bHi, bLo, wrow0, bcol0, 32, 32, 2, lane);

    bar_sync(CGB, 256);
    load_bt_cg(bHi, g_wd1_hi, 128, 64, 64, 0, ctid, rowb);
    load_bt_cg(bLo, g_wd1_lo, 128, 64, 64, 0, ctid, rowb);
    CP_COMMIT();

    bar_sync(RGB, 64);
#pragma unroll
    for (int m = 0; m < 2; m++) {
        int rA = wrow0 + m * 16 + g, rB = rA + 8;
        const float* eA = emb_cat + (size_t)s_cat[rA] * 128;
        const float* eB = emb_cat + (size_t)s_cat[rB] * 128;
#pragma unroll
        for (int nt = 0; nt < 8; nt++) {
            int col = bcol0 + nt * 8 + 2 * t;
            float2 bb = *(const float2*)(projb + col);
            float2 qA = *(const float2*)(eA + col);
            float2 qB = *(const float2*)(eB + col);
            split_pair(aHi, aLo, 136, rA, col,
                       qA.x + lrelu(C[m][nt][0] + bb.x, 0.01f),
                       qA.y + lrelu(C[m][nt][1] + bb.y, 0.01f));
            split_pair(aHi, aLo, 136, rB, col,
                       qB.x + lrelu(C[m][nt][2] + bb.x, 0.01f),
                       qB.y + lrelu(C[m][nt][3] + bb.y, 0.01f));
        }
    }
    bar_sync(RGB, 64);

    // G3
    zeroC2(C);
    warp_gemm2<136>(C, aHi, aLo, bHi, bLo, wrow0, bcol0, 0, 64, 4, lane);
    bar_sync(CGB, 256);
    load_bt_cg(bHi, g_wd2_hi, 128, 0, 64, 64, ctid, rowb);
    load_bt_cg(bLo, g_wd2_lo, 128, 0, 64, 64, ctid, rowb);
    CP_COMMIT();
    CP_WAIT1();
    bar_sync(CGB, 256);
    warp_gemm2<136>(C, aHi, aLo, bHi, bLo, wrow0, bcol0, 64, 0, 4, lane);

    bar_sync(RGB, 64);
#pragma unroll
    for (int m = 0; m < 2; m++) {
        int rA = wrow0 + m * 16 + g, rB = rA + 8;
#pragma unroll
        for (int nt = 0; nt < 8; nt++) {
            int col = bcol0 + nt * 8 + 2 * t;
            float2 bb = *(const float2*)(db1 + col);
            split_pair(aHi, aLo, 136, rA, col,
                       lrelu(C[m][nt][0] + bb.x, 0.1f), lrelu(C[m][nt][1] + bb.y, 0.1f));
            split_pair(aHi, aLo, 136, rB, col,
                       lrelu(C[m][nt][2] + bb.x, 0.1f), lrelu(C[m][nt][3] + bb.y, 0.1f));
        }
    }
    bar_sync(RGB, 64);
    bar_sync(CGB, 256);
    load_bt_cg(bHi, g_wd2_hi, 128, 64, 64, 0, ctid, rowb);
    load_bt_cg(bLo, g_wd2_lo, 128, 64, 64, 0, ctid, rowb);
    CP_COMMIT();
    CP_WAIT1();
    bar_sync(CGB, 256);

    // G4
    zeroC2(C);
    warp_gemm2<136>(C, aHi, aLo, bHi, bLo, wrow0, bcol0, 0, 64, 4, lane);
    CP_WAIT0();
    bar_sync(CGB, 256);
    warp_gemm2<136>(C, aHi, aLo, bHi, bLo, wrow0, bcol0, 64, 0, 4, lane);
#pragma unroll
    for (int m = 0; m < 2; m++) {
        float* oA = out + (base + wrow0 + m * 16 + g) * 128;
        float* oB = oA + 8 * 128;
#pragma unroll
        for (int nt = 0; nt < 8; nt++) {
            int col = bcol0 + nt * 8 + 2 * t;
            float2 bb = *(const float2*)(db2 + col);
            float2 hA = *(const float2*)(oA + col);
            float2 hB = *(const float2*)(oB + col);
            *(float2*)(oA + col) = make_float2(hA.x + lrelu(C[m][nt][0] + bb.x, 0.1f),
                                               hA.y + lrelu(C[m][nt][1] + bb.y, 0.1f));
            *(float2*)(oB + col) = make_float2(hB.x + lrelu(C[m][nt][2] + bb.x, 0.1f),
                                               hB.y + lrelu(C[m][nt][3] + bb.y, 0.1f));
        }
    }
}

// ---------------------------------------------------------------------------
// SAGE conv kernel, round 16: narrow barriers.
// rg = warp pair (rows 32k..32k+32), bar 3+k (64 thr).
// cg = warps with (warp&1)==c (B feature rows 64c..64c+64), bar 1+c (128 thr).
// ---------------------------------------------------------------------------
template <int BLK>
__global__ void __launch_bounds__(256, 1)
conv_kernel(const int* __restrict__ src,
            const float* __restrict__ b1, const float* __restrict__ b2,
            float* __restrict__ d_out)
{
    extern __shared__ char sm[];
    char* aHi = sm;
    char* aLo = aHi + ATC;
    char* bHi = aLo + ATC;
    char* bLo = bHi + BT;
    float* s_red = (float*)(bLo + BT);   // [128][2] final L2 reduce

    const float* h_src = (BLK == 0) ? g_h0 : (BLK == 1) ? g_h1 : g_h2;
    float* h_self      = (BLK == 0) ? g_h1 : (BLK == 1) ? g_h2 : g_h3;
    float* outp        = (BLK == 2) ? d_out : h_self;
    const __nv_bfloat16* w1h = g_wc1_hi + (size_t)BLK * 32768;
    const __nv_bfloat16* w1l = g_wc1_lo + (size_t)BLK * 32768;
    const __nv_bfloat16* w2h = g_wc2_hi + (size_t)BLK * 16384;
    const __nv_bfloat16* w2l = g_wc2_lo + (size_t)BLK * 16384;

    const int tid = threadIdx.x, lane = tid & 31, warp = tid >> 5;
    const int wrow0 = (warp >> 1) * 32, bcol0 = (warp & 1) * 64;
    const int cgid  = warp & 1;
    const int cgtid = ((warp >> 1) << 5) + lane;   // [0,128) within cg
    const int rowb  = cgid * 64;                   // cg's B feature-row half
    const int CGB   = 1 + cgid;                    // 128-thr cg barrier
    const int RGB   = 3 + (warp >> 1);             // 64-thr rg barrier
    const size_t base = (size_t)blockIdx.x * 128;

    // w1 self K-slice -> B (cg's own 64 feature rows)
    load_bt_cg128(bHi, w1h, 256, 0, 128, cgtid, rowb);
    load_bt_cg128(bLo, w1l, 256, 0, 128, cgtid, rowb);
    CP_COMMIT();
    // self rows -> A cols 0..127 (coalesced; 8 rows batched -> MLP 8)
    {
#pragma unroll 1
        for (int rr = 0; rr < 16; rr += 8) {
            float4 q[8];
#pragma unroll
            for (int u = 0; u < 8; u++)
                q[u] = *(const float4*)(h_self + (base + warp * 16 + rr + u) * 128 + lane * 4);
#pragma unroll
            for (int u = 0; u < 8; u++)
                split_quad(aHi, aLo, 264, warp * 16 + rr + u, lane * 4, q[u]);
        }
    }
    bar_sync(RGB, 64);                 // self rows visible within rg pair
    CP_WAIT0();
    bar_sync(CGB, 128);                // whole cg's w1-self landed

    const int g = lane >> 2, t = lane & 3;
    float C[2][8][4];

    // ---- G1a: self half of K=256 ----
    zeroC2(C);
    warp_gemm2<264>(C, aHi, aLo, bHi, bLo, wrow0, bcol0, 0, 0, 8, lane);
    bar_sync(CGB, 128);                // cg done reading B
    load_bt_cg128(bHi, w1h, 256, 128, 128, cgtid, rowb);   // w1 mean K-slice
    load_bt_cg128(bLo, w1l, 256, 128, 128, cgtid, rowb);
    CP_COMMIT();

    // gather-mean (10 consecutive edges, w==10) -> A cols 128..255
    // (edge indices pipelined; validated round 15)
    {
        int idx[10];
        {
            const int* sp = src + (base + warp * 16) * 10;
#pragma unroll
            for (int e = 0; e < 10; e++) idx[e] = sp[e];
        }
#pragma unroll 1
        for (int r = warp * 16; r < warp * 16 + 16; r++) {
            int idxn[10];
            if (r + 1 < warp * 16 + 16) {
                const int* spn = src + (base + r + 1) * 10;
#pragma unroll
                for (int e = 0; e < 10; e++) idxn[e] = spn[e];
            }
            float4 q[10];
#pragma unroll
            for (int e = 0; e < 10; e++)
                q[e] = *(const float4*)(h_src + (size_t)idx[e] * 128 + lane * 4);
            float4 acc = q[0];
#pragma unroll
            for (int e = 1; e < 10; e++) {
                acc.x += q[e].x; acc.y += q[e].y; acc.z += q[e].z; acc.w += q[e].w;
            }
            acc.x *= 0.1f; acc.y *= 0.1f; acc.z *= 0.1f; acc.w *= 0.1f;
            split_quad(aHi, aLo, 264, r, 128 + lane * 4, acc);
#pragma unroll
            for (int e = 0; e < 10; e++) idx[e] = idxn[e];
        }
    }
    bar_sync(RGB, 64);                 // mean rows visible within rg pair
    CP_WAIT0();
    bar_sync(CGB, 128);                // whole cg's w1-mean landed

    // ---- G1b: mean half (accumulate) ----
    warp_gemm2<264>(C, aHi, aLo, bHi, bLo, wrow0, bcol0, 128, 0, 8, lane);
    bar_sync(RGB, 64);                 // rg done reading A (before t overwrite)
    bar_sync(CGB, 128);                // cg done reading B
    load_bt_cg128(bHi, w2h, 128, 0, 128, cgtid, rowb);     // w2
    load_bt_cg128(bLo, w2l, 128, 0, 128, cgtid, rowb);
    CP_COMMIT();

    // t = lrelu(C + b1, 0.1) -> A cols 0..127 (rg rows x cg cols)
#pragma unroll
    for (int m = 0; m < 2; m++) {
        int rA = wrow0 + m * 16 + g, rB = rA + 8;
#pragma unroll
        for (int nt = 0; nt < 8; nt++) {
            int col = bcol0 + nt * 8 + 2 * t;
            float2 bb = *(const float2*)(b1 + col);
            split_pair(aHi, aLo, 264, rA, col,
                       lrelu(C[m][nt][0] + bb.x, 0.1f), lrelu(C[m][nt][1] + bb.y, 0.1f));
            split_pair(aHi, aLo, 264, rB, col,
                       lrelu(C[m][nt][2] + bb.x, 0.1f), lrelu(C[m][nt][3] + bb.y, 0.1f));
        }
    }
    bar_sync(RGB, 64);                 // t visible (rg rows, both col halves in pair)
    CP_WAIT0();
    bar_sync(CGB, 128);                // whole cg's w2 landed

    // ---- G2: res = t @ W2 + b2 ----
    zeroC2(C);
    warp_gemm2<264>(C, aHi, aLo, bHi, bLo, wrow0, bcol0, 0, 0, 8, lane);

    if (BLK != 2) {
#pragma unroll
        for (int m = 0; m < 2; m++) {
            float* oA = outp + (base + wrow0 + m * 16 + g) * 128;
            float* oB = oA + 8 * 128;
#pragma unroll
            for (int nt = 0; nt < 8; nt++) {
                int col = bcol0 + nt * 8 + 2 * t;
                float2 bb = *(const float2*)(b2 + col);
                *(float2*)(oA + col) = make_float2(lrelu(C[m][nt][0] + bb.x, 0.1f),
                                                   lrelu(C[m][nt][1] + bb.y, 0.1f));
                *(float2*)(oB + col) = make_float2(lrelu(C[m][nt][2] + bb.x, 0.1f),
                                                   lrelu(C[m][nt][3] + bb.y, 0.1f));
            }
        }
    } else {
        // add bias, then row-L2-normalize; rows rg-private, cgid within pair
#pragma unroll
        for (int m = 0; m < 2; m++)
#pragma unroll
            for (int nt = 0; nt < 8; nt++) {
                int col = bcol0 + nt * 8 + 2 * t;
                float2 bb = *(const float2*)(b2 + col);
                C[m][nt][0] += bb.x; C[m][nt][1] += bb.y;
                C[m][nt][2] += bb.x; C[m][nt][3] += bb.y;
            }
#pragma unroll
        for (int m = 0; m < 2; m++) {
            int rA = wrow0 + m * 16 + g, rB = rA + 8;
            float pA = 0.0f, pB = 0.0f;
#pragma unroll
            for (int nt = 0; nt < 8; nt++) {
                pA += C[m][nt][0] * C[m][nt][0] + C[m][nt][1] * C[m][nt][1];
                pB += C[m][nt][2] * C[m][nt][2] + C[m][nt][3] * C[m][nt][3];
            }
            pA += __shfl_xor_sync(0xffffffffu, pA, 1);
            pA += __shfl_xor_sync(0xffffffffu, pA, 2);
            pB += __shfl_xor_sync(0xffffffffu, pB, 1);
            pB += __shfl_xor_sync(0xffffffffu, pB, 2);
            if (t == 0) {
                s_red[rA * 2 + cgid] = pA;
                s_red[rB * 2 + cgid] = pB;
            }
        }
        bar_sync(RGB, 64);
#pragma unroll
        for (int m = 0; m < 2; m++) {
            int rA = wrow0 + m * 16 + g, rB = rA + 8;
            float iA = 1.0f / fmaxf(sqrtf(s_red[rA * 2] + s_red[rA * 2 + 1]), 1e-6f);
            float iB = 1.0f / fmaxf(sqrtf(s_red[rB * 2] + s_red[rB * 2 + 1]), 1e-6f);
            float* oA = outp + (base + rA) * 128;
            float* oB = outp + (base + rB) * 128;
#pragma unroll
            for (int nt = 0; nt < 8; nt++) {
                int col = bcol0 + nt * 8 + 2 * t;
                *(float2*)(oA + col) = make_float2(C[m][nt][0] * iA, C[m][nt][1] * iA);
                *(float2*)(oB + col) = make_float2(C[m][nt][2] * iB, C[m][nt][3] * iB);
            }
        }
    }
}

// ---------------------------------------------------------------------------
// host launcher
// ---------------------------------------------------------------------------
extern "C" void kernel_launch(void* const* d_in, const int* in_sizes, int n_in,
                              void* d_out, int out_size)
{
    (void)n_in; (void)out_size;

    const bool dict = (in_sizes[0] == in_sizes[1]);
    int i_nid[4], i_cat[4], i_feat[4], i_src[3];
    if (dict) {
        for (int i = 0; i < 4; i++) { i_nid[i] = 3 * i; i_cat[i] = 3 * i + 1; i_feat[i] = 3 * i + 2; }
        i_src[0] = 12; i_src[1] = 14; i_src[2] = 16;
    } else {
        for (int i = 0; i < 4; i++) { i_nid[i] = i; i_cat[i] = 4 + i; i_feat[i] = 8 + i; }
        i_src[0] = 12; i_src[1] = 13; i_src[2] = 14;
    }
    const float* node_emb = (const float*)d_in[18];
    const float* expW  = (const float*)d_in[19];
    const float* expb  = (const float*)d_in[20];
    const float* emb_cat = (const float*)d_in[21];
    const float* projW = (const float*)d_in[22];
    const float* projb = (const float*)d_in[23];
    const float* dW1 = (const float*)d_in[24];
    const float* db1 = (const float*)d_in[25];
    const float* dW2 = (const float*)d_in[26];
    const float* db2 = (const float*)d_in[27];
    const float* cW1 = (const float*)d_in[28];
    const float* cb1 = (const float*)d_in[29];
    const float* cW2 = (const float*)d_in[30];
    const float* cb2 = (const float*)d_in[31];

    cudaFuncSetAttribute(node_kernel, cudaFuncAttributeMaxDynamicSharedMemorySize, NODE_SMEM);
    cudaFuncSetAttribute(conv_kernel<0>, cudaFuncAttributeMaxDynamicSharedMemorySize, CONV_SMEM);
    cudaFuncSetAttribute(conv_kernel<1>, cudaFuncAttributeMaxDynamicSharedMemorySize, CONV_SMEM);
    cudaFuncSetAttribute(conv_kernel<2>, cudaFuncAttributeMaxDynamicSharedMemorySize, CONV_SMEM);

    prep_weights<<<(188416 + 255) / 256, 256>>>(expW, projW, dW1, dW2, cW1, cW2);

    NodeArgs na;
    na.nid0 = (const int*)d_in[i_nid[0]];  na.nid1 = (const int*)d_in[i_nid[1]];
    na.nid2 = (const int*)d_in[i_nid[2]];  na.nid3 = (const int*)d_in[i_nid[3]];
    na.cat0 = (const int*)d_in[i_cat[0]];  na.cat1 = (const int*)d_in[i_cat[1]];
    na.cat2 = (const int*)d_in[i_cat[2]];  na.cat3 = (const int*)d_in[i_cat[3]];
    na.feat0 = (const float*)d_in[i_feat[0]];  na.feat1 = (const float*)d_in[i_feat[1]];
    na.feat2 = (const float*)d_in[i_feat[2]];  na.feat3 = (const float*)d_in[i_feat[3]];

    node_kernel<<<NODE_BLOCKS, 512, NODE_SMEM>>>(na, node_emb, expb, emb_cat,
                                                 projb, db1, db2);

    conv_kernel<0><<<L1 / 128, 256, CONV_SMEM>>>((const int*)d_in[i_src[0]],
        cb1 + 0 * 128, cb2 + 0 * 128, (float*)d_out);
    conv_kernel<1><<<L2 / 128, 256, CONV_SMEM>>>((const int*)d_in[i_src[1]],
        cb1 + 1 * 128, cb2 + 1 * 128, (float*)d_out);
    conv_kernel<2><<<L3 / 128, 256, CONV_SMEM>>>((const int*)d_in[i_src[2]],
        cb1 + 2 * 128, cb2 + 2 * 128, (float*)d_out);
}

// round 17
// speedup vs baseline: 1.0045x; 1.0045x over previous
#include <cuda_runtime.h>
#include <cuda_bf16.h>
#include <cstdint>
#include <math.h>

// ---------------------------------------------------------------------------
// GraphSageWithSampling — warp-mma bf16 split-precision, round 17
// = round 15 (988.4us, best) with conv restored verbatim (round-16 narrow
//   conv barriers were neutral -> reverted) + one free hoist: the FIRST
//   gather row's edge indices load BEFORE G1a, hiding their ~600cyc latency
//   behind the self-half GEMM (round 15 only pipelined rows 1..15).
// Node kernel: byte-identical to rounds 14/15 (protected win).
// Numerics bit-identical; rel_err canary 1.058542e-5.
// ---------------------------------------------------------------------------

namespace {
constexpr int L0 = 524288, L1 = 131072, L2 = 32768, L3 = 8192;
}

// scratch activations
__device__ float g_h0[(long long)L0 * 128];
__device__ float g_h1[(long long)L1 * 128];
__device__ float g_h2[(long long)L2 * 128];
__device__ float g_h3[(long long)L3 * 128];

// pre-split, pre-transposed weights: [F=128][K] row-major, hi/lo bf16
__device__ __nv_bfloat16 g_wexp_hi[128 * 32],  g_wexp_lo[128 * 32];
__device__ __nv_bfloat16 g_wproj_hi[128 * 32], g_wproj_lo[128 * 32];
__device__ __nv_bfloat16 g_wd1_hi[128 * 128],  g_wd1_lo[128 * 128];
__device__ __nv_bfloat16 g_wd2_hi[128 * 128],  g_wd2_lo[128 * 128];
__device__ __nv_bfloat16 g_wc1_hi[3 * 128 * 256], g_wc1_lo[3 * 128 * 256];
__device__ __nv_bfloat16 g_wc2_hi[3 * 128 * 128], g_wc2_lo[3 * 128 * 128];

__device__ __forceinline__ uint32_t smem_u32(const void* p) {
    uint32_t a;
    asm("{ .reg .u64 t; cvta.to.shared.u64 t, %1; cvt.u32.u64 %0, t; }" : "=r"(a) : "l"(p));
    return a;
}
__device__ __forceinline__ float lrelu(float x, float s) { return x >= 0.0f ? x : x * s; }

__device__ __forceinline__ void bar_sync(int id, int cnt) {
    asm volatile("bar.sync %0, %1;" :: "r"(id), "r"(cnt) : "memory");
}

__device__ __forceinline__ void ldsm4(unsigned (&r)[4], uint32_t a) {
    asm volatile("ldmatrix.sync.aligned.m8n8.x4.shared.b16 {%0,%1,%2,%3}, [%4];"
                 : "=r"(r[0]), "=r"(r[1]), "=r"(r[2]), "=r"(r[3]) : "r"(a));
}
__device__ __forceinline__ void mma_bf16(float (&c)[4], const unsigned (&a)[4],
                                         unsigned b0, unsigned b1) {
    asm("mma.sync.aligned.m16n8k16.row.col.f32.bf16.bf16.f32 "
        "{%0,%1,%2,%3}, {%4,%5,%6,%7}, {%8,%9}, {%0,%1,%2,%3};"
        : "+f"(c[0]), "+f"(c[1]), "+f"(c[2]), "+f"(c[3])
        : "r"(a[0]), "r"(a[1]), "r"(a[2]), "r"(a[3]), "r"(b0), "r"(b1));
}
__device__ __forceinline__ void cp16(uint32_t saddr, const void* g) {
    asm volatile("cp.async.cg.shared.global [%0], [%1], 16;" :: "r"(saddr), "l"(g));
}
#define CP_COMMIT() asm volatile("cp.async.commit_group;" ::: "memory")
#define CP_WAIT0()  asm volatile("cp.async.wait_group 0;" ::: "memory")
#define CP_WAIT1()  asm volatile("cp.async.wait_group 1;" ::: "memory")

__device__ __forceinline__ void zeroC2(float (&C)[2][8][4]) {
#pragma unroll
    for (int m = 0; m < 2; m++)
#pragma unroll
        for (int i = 0; i < 8; i++)
#pragma unroll
            for (int j = 0; j < 4; j++) C[m][i][j] = 0.0f;
}

// split fp32 pair -> hi/lo bf16 pairs (u32 each) into strided tiles
__device__ __forceinline__ void split_pair(char* hi, char* lo, int stride,
                                           int row, int col, float x0, float x1) {
    __nv_bfloat16 h0 = __float2bfloat16(x0), h1 = __float2bfloat16(x1);
    __nv_bfloat16 l0 = __float2bfloat16(x0 - __bfloat162float(h0));
    __nv_bfloat16 l1 = __float2bfloat16(x1 - __bfloat162float(h1));
    int off = (row * stride + col) * 2;
    *(uint32_t*)(hi + off) = (uint32_t)__bfloat16_as_ushort(h0) |
                             ((uint32_t)__bfloat16_as_ushort(h1) << 16);
    *(uint32_t*)(lo + off) = (uint32_t)__bfloat16_as_ushort(l0) |
                             ((uint32_t)__bfloat16_as_ushort(l1) << 16);
}

// split fp32 quad -> hi/lo bf16, single uint2 (STS.64) per tile.
__device__ __forceinline__ void split_quad(char* hi, char* lo, int stride,
                                           int row, int col, float4 q) {
    __nv_bfloat16 h0 = __float2bfloat16(q.x), h1 = __float2bfloat16(q.y);
    __nv_bfloat16 h2 = __float2bfloat16(q.z), h3 = __float2bfloat16(q.w);
    __nv_bfloat16 l0 = __float2bfloat16(q.x - __bfloat162float(h0));
    __nv_bfloat16 l1 = __float2bfloat16(q.y - __bfloat162float(h1));
    __nv_bfloat16 l2 = __float2bfloat16(q.z - __bfloat162float(h2));
    __nv_bfloat16 l3 = __float2bfloat16(q.w - __bfloat162float(h3));
    int off = (row * stride + col) * 2;
    uint2 hv, lv;
    hv.x = (uint32_t)__bfloat16_as_ushort(h0) | ((uint32_t)__bfloat16_as_ushort(h1) << 16);
    hv.y = (uint32_t)__bfloat16_as_ushort(h2) | ((uint32_t)__bfloat16_as_ushort(h3) << 16);
    lv.x = (uint32_t)__bfloat16_as_ushort(l0) | ((uint32_t)__bfloat16_as_ushort(l1) << 16);
    lv.y = (uint32_t)__bfloat16_as_ushort(l2) | ((uint32_t)__bfloat16_as_ushort(l3) << 16);
    *(uint2*)(hi + off) = hv;
    *(uint2*)(lo + off) = lv;
}

// full-CTA cp.async copy of [128][ncols] weights into B tile (stride 136)
template <int NT>
__device__ __forceinline__ void load_bt(char* dst, const __nv_bfloat16* __restrict__ g,
                                        int gStride, int gcol0, int ncols, int dcol0, int tid) {
    const int vec = ncols >> 3;
    const uint32_t db = smem_u32(dst);
    for (int i = tid; i < 128 * vec; i += NT) {
        int f = i / vec, j = (i - f * vec) * 8;
        cp16(db + (uint32_t)(f * 136 + dcol0 + j) * 2, g + (size_t)f * gStride + gcol0 + j);
    }
}

// cg-scoped cp.async copy (node kernel): cg's 64 feature rows [rowbase..+64)
__device__ __forceinline__ void load_bt_cg(char* dst, const __nv_bfloat16* __restrict__ g,
                                           int gStride, int gcol0, int ncols, int dcol0,
                                           int ctid, int rowbase) {
    const int vec = ncols >> 3;
    const uint32_t db = smem_u32(dst);
    for (int i = ctid; i < 64 * vec; i += 256) {
        int r = i / vec, j = (i - r * vec) * 8;
        int f = rowbase + r;
        cp16(db + (uint32_t)(f * 136 + dcol0 + j) * 2, g + (size_t)f * gStride + gcol0 + j);
    }
}

// warp GEMM, 32x64 tile: C[2 m-tiles][8 n8][4] += 3-way split product.
template <int SA>
__device__ __forceinline__ void warp_gemm2(float (&C)[2][8][4],
                                           const char* aHi, const char* aLo,
                                           const char* bHi, const char* bLo,
                                           int wrow0, int bcol0, int aCol0, int bCol0,
                                           int nkb, int lane)
{
    const int lr = lane & 7, quad = lane >> 3;
    const uint32_t aBH = smem_u32(aHi), aBL = smem_u32(aLo);
    const uint32_t bBH = smem_u32(bHi), bBL = smem_u32(bLo);
    const uint32_t aR0 =
        (uint32_t)(((wrow0 + ((quad & 1) << 3) + lr) * SA) + ((quad >> 1) << 3) + aCol0) * 2;
    const uint32_t aR1 = aR0 + (uint32_t)(16 * SA * 2);
    const int bRow = bcol0 + ((quad >> 1) << 3) + lr;
    const int bCol = ((quad & 1) << 3) + bCol0;
#pragma unroll 1
    for (int kb = 0; kb < nkb; kb++) {
        unsigned ah[2][4], al[2][4];
        uint32_t ak = (uint32_t)(kb * 32);
        ldsm4(ah[0], aBH + aR0 + ak);
        ldsm4(al[0], aBL + aR0 + ak);
        ldsm4(ah[1], aBH + aR1 + ak);
        ldsm4(al[1], aBL + aR1 + ak);
        unsigned bh[2][4], bl[2][4];
        uint32_t bo0 = (uint32_t)((bRow * 136) + bCol + kb * 16) * 2;
        ldsm4(bh[0], bBH + bo0);
        ldsm4(bl[0], bBL + bo0);
#pragma unroll
        for (int ntp = 0; ntp < 4; ntp++) {
            const int cur = ntp & 1, nxt = cur ^ 1;
            if (ntp < 3) {
                uint32_t bo = bo0 + (uint32_t)((ntp + 1) * 16 * 136) * 2;
                ldsm4(bh[nxt], bBH + bo);
                ldsm4(bl[nxt], bBL + bo);
            }
#pragma unroll
            for (int p = 0; p < 3; p++) {
#pragma unroll
                for (int m = 0; m < 2; m++) {
                    const unsigned (&A)[4] = (p == 1) ? al[m] : ah[m];
                    const unsigned*  B     = (p == 2) ? bl[cur] : bh[cur];
                    mma_bf16(C[m][2 * ntp],     A, B[0], B[1]);
                    mma_bf16(C[m][2 * ntp + 1], A, B[2], B[3]);
                }
            }
        }
    }
}

// ---------------------------------------------------------------------------
// prep kernel (unchanged, validated)
// ---------------------------------------------------------------------------
__global__ void prep_weights(const float* __restrict__ expW, const float* __restrict__ projW,
                             const float* __restrict__ dW1, const float* __restrict__ dW2,
                             const float* __restrict__ cW1, const float* __restrict__ cW2)
{
    int i = blockIdx.x * blockDim.x + threadIdx.x;
    float val; __nv_bfloat16 *dh, *dl; int di;
    if (i < 4096)        { int f = i >> 5,  k = i & 31;  val = expW[k * 128 + f];  dh = g_wexp_hi;  dl = g_wexp_lo;  di = i; }
    else if (i < 8192)   { int j = i - 4096;  int f = j >> 5,  k = j & 31;  val = projW[k * 128 + f]; dh = g_wproj_hi; dl = g_wproj_lo; di = j; }
    else if (i < 24576)  { int j = i - 8192;  int f = j >> 7,  k = j & 127; val = dW1[k * 128 + f];  dh = g_wd1_hi;  dl = g_wd1_lo;  di = j; }
    else if (i < 40960)  { int j = i - 24576; int f = j >> 7,  k = j & 127; val = dW2[k * 128 + f];  dh = g_wd2_hi;  dl = g_wd2_lo;  di = j; }
    else if (i < 139264) { int j = i - 40960; int b = j >> 15; int r = j & 32767; int f = r >> 8, k = r & 255;
                           val = cW1[(size_t)b * 32768 + k * 128 + f]; dh = g_wc1_hi; dl = g_wc1_lo; di = j; }
    else if (i < 188416) { int j = i - 139264; int b = j / 16384; int r = j - b * 16384; int f = r >> 7, k = r & 127;
                           val = cW2[(size_t)b * 16384 + k * 128 + f]; dh = g_wc2_hi; dl = g_wc2_lo; di = j; }
    else return;
    __nv_bfloat16 h = __float2bfloat16(val);
    dh[di] = h;
    dl[di] = __float2bfloat16(val - __bfloat162float(h));
}

namespace {
constexpr int BT  = 34816;                          // B tile 128x136 bf16
constexpr int ATn = 69632;                          // node A tile 256x136 bf16
constexpr int NODE_SMEM = 2 * ATn + 2 * BT + 1024;  // 209,920 B
constexpr int ATC = 67584;                          // conv A tile 128x264 bf16
constexpr int CONV_SMEM = 2 * ATC + 2 * BT + 1024;  // 205,824 B
constexpr int NB0 = 2048, NB1 = 512, NB2 = 128, NB3 = 32;    // 256-row blocks
constexpr int NODE_BLOCKS = NB0 + NB1 + NB2 + NB3;           // 2720
}

struct NodeArgs {
    const int *nid0, *nid1, *nid2, *nid3;
    const int *cat0, *cat1, *cat2, *cat3;
    const float *feat0, *feat1, *feat2, *feat3;
};

// ---------------------------------------------------------------------------
// Merged node transform kernel (UNCHANGED rounds 14/15 winning config).
// ---------------------------------------------------------------------------
__global__ void __launch_bounds__(512, 1)
node_kernel(NodeArgs A_,
            const float* __restrict__ node_emb,
            const float* __restrict__ expb, const float* __restrict__ emb_cat,
            const float* __restrict__ projb, const float* __restrict__ db1,
            const float* __restrict__ db2)
{
    extern __shared__ char sm[];
    char* aHi = sm;
    char* aLo = aHi + ATn;
    char* bHi = aLo + ATn;
    char* bLo = bHi + BT;
    int* s_cat = (int*)(bLo + BT);

    const int b = blockIdx.x;
    const int*   nid;  const int* cat;  const float* feat;  float* out;  size_t base;
    if (b < NB0)              { nid = A_.nid0; cat = A_.cat0; feat = A_.feat0; out = g_h0; base = (size_t)b * 256; }
    else if (b < NB0 + NB1)   { nid = A_.nid1; cat = A_.cat1; feat = A_.feat1; out = g_h1; base = (size_t)(b - NB0) * 256; }
    else if (b < NB0 + NB1 + NB2) { nid = A_.nid2; cat = A_.cat2; feat = A_.feat2; out = g_h2; base = (size_t)(b - NB0 - NB1) * 256; }
    else                      { nid = A_.nid3; cat = A_.cat3; feat = A_.feat3; out = g_h3; base = (size_t)(b - NB0 - NB1 - NB2) * 256; }

    const int tid = threadIdx.x, lane = tid & 31, warp = tid >> 5;
    const int wrow0 = (warp >> 1) * 32, bcol0 = (warp & 1) * 64;
    const int cgid  = warp & 1;
    const int ctid  = ((warp >> 1) << 5) + lane;
    const int rowb  = cgid * 64;
    const int CGB   = 1 + cgid;
    const int RGB   = 3 + (warp >> 1);

    if (tid < 256) s_cat[tid] = cat[base + tid];

    load_bt_cg(bHi, g_wexp_hi, 32, 0, 32, 0, ctid, rowb);
    load_bt_cg(bLo, g_wexp_lo, 32, 0, 32, 0, ctid, rowb);
    load_bt_cg(bHi, g_wproj_hi, 32, 0, 32, 32, ctid, rowb);
    load_bt_cg(bLo, g_wproj_lo, 32, 0, 32, 32, ctid, rowb);
    load_bt_cg(bHi, g_wd1_hi, 128, 0, 64, 64, ctid, rowb);
    load_bt_cg(bLo, g_wd1_lo, 128, 0, 64, 64, ctid, rowb);
    CP_COMMIT();

    // inputs: 8 LDG.128 batched (MLP 8), STS.64 stores
    {
        int row = tid >> 1, half = tid & 1;
        const float4* e4 = (const float4*)(node_emb + (size_t)(nid[base + row] + 1) * 32 + half * 16);
        const float4* f4 = (const float4*)(feat + (base + row) * 32 + half * 16);
        float4 qe[4], qf[4];
#pragma unroll
        for (int j = 0; j < 4; j++) qe[j] = e4[j];
#pragma unroll
        for (int j = 0; j < 4; j++) qf[j] = f4[j];
#pragma unroll
        for (int j = 0; j < 4; j++)
            split_quad(aHi, aLo, 136, row, half * 16 + 4 * j, qe[j]);
#pragma unroll
        for (int j = 0; j < 4; j++)
            split_quad(aHi, aLo, 136, row, 32 + half * 16 + 4 * j, qf[j]);
    }
    CP_WAIT0();
    __syncthreads();

    const int g = lane >> 2, t = lane & 3;
    float C[2][8][4];

    // G1
    zeroC2(C);
    warp_gemm2<136>(C, aHi, aLo, bHi, bLo, wrow0, bcol0, 0, 0, 2, lane);
#pragma unroll
    for (int m = 0; m < 2; m++) {
        float* oA = out + (base + wrow0 + m * 16 + g) * 128;
        float* oB = oA + 8 * 128;
#pragma unroll
        for (int nt = 0; nt < 8; nt++) {
            int col = bcol0 + nt * 8 + 2 * t;
            float2 bb = *(const float2*)(expb + col);
            *(float2*)(oA + col) = make_float2(lrelu(C[m][nt][0] + bb.x, 0.1f),
                                               lrelu(C[m][nt][1] + bb.y, 0.1f));
            *(float2*)(oB + col) = make_float2(lrelu(C[m][nt][2] + bb.x, 0.1f),
                                               lrelu(C[m][nt][3] + bb.y, 0.1f));
        }
    }

    // G2
    zeroC2(C);
    warp_gemm2<136>(C, aHi, aLo, bHi, bLo, wrow0, bcol0, 32, 32, 2, lane);

    bar_sync(CGB, 256);
    load_bt_cg(bHi, g_wd1_hi, 128, 64, 64, 0, ctid, rowb);
    load_bt_cg(bLo, g_wd1_lo, 128, 64, 64, 0, ctid, rowb);
    CP_COMMIT();

    bar_sync(RGB, 64);
#pragma unroll
    for (int m = 0; m < 2; m++) {
        int rA = wrow0 + m * 16 + g, rB = rA + 8;
        const float* eA = emb_cat + (size_t)s_cat[rA] * 128;
        const float* eB = emb_cat + (size_t)s_cat[rB] * 128;
#pragma unroll
        for (int nt = 0; nt < 8; nt++) {
            int col = bcol0 + nt * 8 + 2 * t;
            float2 bb = *(const float2*)(projb + col);
            float2 qA = *(const float2*)(eA + col);
            float2 qB = *(const float2*)(eB + col);
            split_pair(aHi, aLo, 136, rA, col,
                       qA.x + lrelu(C[m][nt][0] + bb.x, 0.01f),
                       qA.y + lrelu(C[m][nt][1] + bb.y, 0.01f));
            split_pair(aHi, aLo, 136, rB, col,
                       qB.x + lrelu(C[m][nt][2] + bb.x, 0.01f),
                       qB.y + lrelu(C[m][nt][3] + bb.y, 0.01f));
        }
    }
    bar_sync(RGB, 64);

    // G3
    zeroC2(C);
    warp_gemm2<136>(C, aHi, aLo, bHi, bLo, wrow0, bcol0, 0, 64, 4, lane);
    bar_sync(CGB, 256);
    load_bt_cg(bHi, g_wd2_hi, 128, 0, 64, 64, ctid, rowb);
    load_bt_cg(bLo, g_wd2_lo, 128, 0, 64, 64, ctid, rowb);
    CP_COMMIT();
    CP_WAIT1();
    bar_sync(CGB, 256);
    warp_gemm2<136>(C, aHi, aLo, bHi, bLo, wrow0, bcol0, 64, 0, 4, lane);

    bar_sync(RGB, 64);
#pragma unroll
    for (int m = 0; m < 2; m++) {
        int rA = wrow0 + m * 16 + g, rB = rA + 8;
#pragma unroll
        for (int nt = 0; nt < 8; nt++) {
            int col = bcol0 + nt * 8 + 2 * t;
            float2 bb = *(const float2*)(db1 + col);
            split_pair(aHi, aLo, 136, rA, col,
                       lrelu(C[m][nt][0] + bb.x, 0.1f), lrelu(C[m][nt][1] + bb.y, 0.1f));
            split_pair(aHi, aLo, 136, rB, col,
                       lrelu(C[m][nt][2] + bb.x, 0.1f), lrelu(C[m][nt][3] + bb.y, 0.1f));
        }
    }
    bar_sync(RGB, 64);
    bar_sync(CGB, 256);
    load_bt_cg(bHi, g_wd2_hi, 128, 64, 64, 0, ctid, rowb);
    load_bt_cg(bLo, g_wd2_lo, 128, 64, 64, 0, ctid, rowb);
    CP_COMMIT();
    CP_WAIT1();
    bar_sync(CGB, 256);

    // G4
    zeroC2(C);
    warp_gemm2<136>(C, aHi, aLo, bHi, bLo, wrow0, bcol0, 0, 64, 4, lane);
    CP_WAIT0();
    bar_sync(CGB, 256);
    warp_gemm2<136>(C, aHi, aLo, bHi, bLo, wrow0, bcol0, 64, 0, 4, lane);
#pragma unroll
    for (int m = 0; m < 2; m++) {
        float* oA = out + (base + wrow0 + m * 16 + g) * 128;
        float* oB = oA + 8 * 128;
#pragma unroll
        for (int nt = 0; nt < 8; nt++) {
            int col = bcol0 + nt * 8 + 2 * t;
            float2 bb = *(const float2*)(db2 + col);
            float2 hA = *(const float2*)(oA + col);
            float2 hB = *(const float2*)(oB + col);
            *(float2*)(oA + col) = make_float2(hA.x + lrelu(C[m][nt][0] + bb.x, 0.1f),
                                               hA.y + lrelu(C[m][nt][1] + bb.y, 0.1f));
            *(float2*)(oB + col) = make_float2(hB.x + lrelu(C[m][nt][2] + bb.x, 0.1f),
                                               hB.y + lrelu(C[m][nt][3] + bb.y, 0.1f));
        }
    }
}

// ---------------------------------------------------------------------------
// SAGE conv kernel: round-15 structure (validated best); first gather row's
// edge indices hoisted above G1a so their latency hides behind the GEMM.
// ---------------------------------------------------------------------------
template <int BLK>
__global__ void __launch_bounds__(256, 1)
conv_kernel(const int* __restrict__ src,
            const float* __restrict__ b1, const float* __restrict__ b2,
            float* __restrict__ d_out)
{
    extern __shared__ char sm[];
    char* aHi = sm;
    char* aLo = aHi + ATC;
    char* bHi = aLo + ATC;
    char* bLo = bHi + BT;
    float* s_red = (float*)(bLo + BT);   // [128][2] final L2 reduce

    const float* h_src = (BLK == 0) ? g_h0 : (BLK == 1) ? g_h1 : g_h2;
    float* h_self      = (BLK == 0) ? g_h1 : (BLK == 1) ? g_h2 : g_h3;
    float* outp        = (BLK == 2) ? d_out : h_self;
    const __nv_bfloat16* w1h = g_wc1_hi + (size_t)BLK * 32768;
    const __nv_bfloat16* w1l = g_wc1_lo + (size_t)BLK * 32768;
    const __nv_bfloat16* w2h = g_wc2_hi + (size_t)BLK * 16384;
    const __nv_bfloat16* w2l = g_wc2_lo + (size_t)BLK * 16384;

    const int tid = threadIdx.x, lane = tid & 31, warp = tid >> 5;
    const int wrow0 = (warp >> 1) * 32, bcol0 = (warp & 1) * 64;
    const size_t base = (size_t)blockIdx.x * 128;

    load_bt<256>(bHi, w1h, 256, 0, 128, 0, tid);
    load_bt<256>(bLo, w1l, 256, 0, 128, 0, tid);
    CP_COMMIT();
    // self rows -> A cols 0..127 (coalesced; 8 rows batched -> MLP 8)
    {
#pragma unroll 1
        for (int rr = 0; rr < 16; rr += 8) {
            float4 q[8];
#pragma unroll
            for (int u = 0; u < 8; u++)
                q[u] = *(const float4*)(h_self + (base + warp * 16 + rr + u) * 128 + lane * 4);
#pragma unroll
            for (int u = 0; u < 8; u++)
                split_quad(aHi, aLo, 264, warp * 16 + rr + u, lane * 4, q[u]);
        }
    }
    CP_WAIT0();
    __syncthreads();

    const int g = lane >> 2, t = lane & 3;
    float C[2][8][4];

    // HOISTED: first gather row's edge indices load before G1a (no deps);
    // their ~600cyc latency hides behind the 8-kb self GEMM.
    int idx[10];
    {
        const int* sp = src + (base + warp * 16) * 10;
#pragma unroll
        for (int e = 0; e < 10; e++) idx[e] = sp[e];
    }

    // ---- G1a: self half of K=256 ----
    zeroC2(C);
    warp_gemm2<264>(C, aHi, aLo, bHi, bLo, wrow0, bcol0, 0, 0, 8, lane);
    __syncthreads();
    load_bt<256>(bHi, w1h, 256, 128, 128, 0, tid);
    load_bt<256>(bLo, w1l, 256, 128, 128, 0, tid);
    CP_COMMIT();

    // gather-mean (10 consecutive edges, w==10) -> A cols 128..255
    // (coalesced warp-per-row; edge indices pipelined across rows)
    {
#pragma unroll 1
        for (int r = warp * 16; r < warp * 16 + 16; r++) {
            int idxn[10];
            if (r + 1 < warp * 16 + 16) {
                const int* spn = src + (base + r + 1) * 10;
#pragma unroll
                for (int e = 0; e < 10; e++) idxn[e] = spn[e];
            }
            float4 q[10];
#pragma unroll
            for (int e = 0; e < 10; e++)
                q[e] = *(const float4*)(h_src + (size_t)idx[e] * 128 + lane * 4);
            float4 acc = q[0];
#pragma unroll
            for (int e = 1; e < 10; e++) {
                acc.x += q[e].x; acc.y += q[e].y; acc.z += q[e].z; acc.w += q[e].w;
            }
            acc.x *= 0.1f; acc.y *= 0.1f; acc.z *= 0.1f; acc.w *= 0.1f;
            split_quad(aHi, aLo, 264, r, 128 + lane * 4, acc);
#pragma unroll
            for (int e = 0; e < 10; e++) idx[e] = idxn[e];
        }
    }
    CP_WAIT0();
    __syncthreads();

    // ---- G1b: mean half (accumulate) ----
    warp_gemm2<264>(C, aHi, aLo, bHi, bLo, wrow0, bcol0, 128, 0, 8, lane);
    __syncthreads();
    load_bt<256>(bHi, w2h, 128, 0, 128, 0, tid);
    load_bt<256>(bLo, w2l, 128, 0, 128, 0, tid);
    CP_COMMIT();

    // t = lrelu(C + b1, 0.1) -> A cols 0..127
#pragma unroll
    for (int m = 0; m < 2; m++) {
        int rA = wrow0 + m * 16 + g, rB = rA + 8;
#pragma unroll
        for (int nt = 0; nt < 8; nt++) {
            int col = bcol0 + nt * 8 + 2 * t;
            float2 bb = *(const float2*)(b1 + col);
            split_pair(aHi, aLo, 264, rA, col,
                       lrelu(C[m][nt][0] + bb.x, 0.1f), lrelu(C[m][nt][1] + bb.y, 0.1f));
            split_pair(aHi, aLo, 264, rB, col,
                       lrelu(C[m][nt][2] + bb.x, 0.1f), lrelu(C[m][nt][3] + bb.y, 0.1f));
        }
    }
    CP_WAIT0();
    __syncthreads();

    // ---- G2: res = t @ W2 + b2 ----
    zeroC2(C);
    warp_gemm2<264>(C, aHi, aLo, bHi, bLo, wrow0, bcol0, 0, 0, 8, lane);

    if (BLK != 2) {
#pragma unroll
        for (int m = 0; m < 2; m++) {
            float* oA = outp + (base + wrow0 + m * 16 + g) * 128;
            float* oB = oA + 8 * 128;
#pragma unroll
            for (int nt = 0; nt < 8; nt++) {
                int col = bcol0 + nt * 8 + 2 * t;
                float2 bb = *(const float2*)(b2 + col);
                *(float2*)(oA + col) = make_float2(lrelu(C[m][nt][0] + bb.x, 0.1f),
                                                   lrelu(C[m][nt][1] + bb.y, 0.1f));
                *(float2*)(oB + col) = make_float2(lrelu(C[m][nt][2] + bb.x, 0.1f),
                                                   lrelu(C[m][nt][3] + bb.y, 0.1f));
            }
        }
    } else {
#pragma unroll
        for (int m = 0; m < 2; m++)
#pragma unroll
            for (int nt = 0; nt < 8; nt++) {
                int col = bcol0 + nt * 8 + 2 * t;
                float2 bb = *(const float2*)(b2 + col);
                C[m][nt][0] += bb.x; C[m][nt][1] += bb.y;
                C[m][nt][2] += bb.x; C[m][nt][3] += bb.y;
            }
        __syncthreads();
#pragma unroll
        for (int m = 0; m < 2; m++) {
            float pA = 0.0f, pB = 0.0f;
#pragma unroll
            for (int nt = 0; nt < 8; nt++) {
                pA += C[m][nt][0] * C[m][nt][0] + C[m][nt][1] * C[m][nt][1];
                pB += C[m][nt][2] * C[m][nt][2] + C[m][nt][3] * C[m][nt][3];
            }
            pA += __shfl_xor_sync(0xffffffffu, pA, 1);
            pA += __shfl_xor_sync(0xffffffffu, pA, 2);
            pB += __shfl_xor_sync(0xffffffffu, pB, 1);
            pB += __shfl_xor_sync(0xffffffffu, pB, 2);
            if (t == 0) {
                s_red[(wrow0 + m * 16 + g) * 2 + (warp & 1)] = pA;
                s_red[(wrow0 + m * 16 + 8 + g) * 2 + (warp & 1)] = pB;
            }
        }
        __syncthreads();
#pragma unroll
        for (int m = 0; m < 2; m++) {
            int rA = wrow0 + m * 16 + g, rB = rA + 8;
            float iA = 1.0f / fmaxf(sqrtf(s_red[rA * 2] + s_red[rA * 2 + 1]), 1e-6f);
            float iB = 1.0f / fmaxf(sqrtf(s_red[rB * 2] + s_red[rB * 2 + 1]), 1e-6f);
            float* oA = outp + (base + rA) * 128;
            float* oB = outp + (base + rB) * 128;
#pragma unroll
            for (int nt = 0; nt < 8; nt++) {
                int col = bcol0 + nt * 8 + 2 * t;
                *(float2*)(oA + col) = make_float2(C[m][nt][0] * iA, C[m][nt][1] * iA);
                *(float2*)(oB + col) = make_float2(C[m][nt][2] * iB, C[m][nt][3] * iB);
            }
        }
    }
}

// ---------------------------------------------------------------------------
// host launcher
// ---------------------------------------------------------------------------
extern "C" void kernel_launch(void* const* d_in, const int* in_sizes, int n_in,
                              void* d_out, int out_size)
{
    (void)n_in; (void)out_size;

    const bool dict = (in_sizes[0] == in_sizes[1]);
    int i_nid[4], i_cat[4], i_feat[4], i_src[3];
    if (dict) {
        for (int i = 0; i < 4; i++) { i_nid[i] = 3 * i; i_cat[i] = 3 * i + 1; i_feat[i] = 3 * i + 2; }
        i_src[0] = 12; i_src[1] = 14; i_src[2] = 16;
    } else {
        for (int i = 0; i < 4; i++) { i_nid[i] = i; i_cat[i] = 4 + i; i_feat[i] = 8 + i; }
        i_src[0] = 12; i_src[1] = 13; i_src[2] = 14;
    }
    const float* node_emb = (const float*)d_in[18];
    const float* expW  = (const float*)d_in[19];
    const float* expb  = (const float*)d_in[20];
    const float* emb_cat = (const float*)d_in[21];
    const float* projW = (const float*)d_in[22];
    const float* projb = (const float*)d_in[23];
    const float* dW1 = (const float*)d_in[24];
    const float* db1 = (const float*)d_in[25];
    const float* dW2 = (const float*)d_in[26];
    const float* db2 = (const float*)d_in[27];
    const float* cW1 = (const float*)d_in[28];
    const float* cb1 = (const float*)d_in[29];
    const float* cW2 = (const float*)d_in[30];
    const float* cb2 = (const float*)d_in[31];

    cudaFuncSetAttribute(node_kernel, cudaFuncAttributeMaxDynamicSharedMemorySize, NODE_SMEM);
    cudaFuncSetAttribute(conv_kernel<0>, cudaFuncAttributeMaxDynamicSharedMemorySize, CONV_SMEM);
    cudaFuncSetAttribute(conv_kernel<1>, cudaFuncAttributeMaxDynamicSharedMemorySize, CONV_SMEM);
    cudaFuncSetAttribute(conv_kernel<2>, cudaFuncAttributeMaxDynamicSharedMemorySize, CONV_SMEM);

    prep_weights<<<(188416 + 255) / 256, 256>>>(expW, projW, dW1, dW2, cW1, cW2);

    NodeArgs na;
    na.nid0 = (const int*)d_in[i_nid[0]];  na.nid1 = (const int*)d_in[i_nid[1]];
    na.nid2 = (const int*)d_in[i_nid[2]];  na.nid3 = (const int*)d_in[i_nid[3]];
    na.cat0 = (const int*)d_in[i_cat[0]];  na.cat1 = (const int*)d_in[i_cat[1]];
    na.cat2 = (const int*)d_in[i_cat[2]];  na.cat3 = (const int*)d_in[i_cat[3]];
    na.feat0 = (const float*)d_in[i_feat[0]];  na.feat1 = (const float*)d_in[i_feat[1]];
    na.feat2 = (const float*)d_in[i_feat[2]];  na.feat3 = (const float*)d_in[i_feat[3]];

    node_kernel<<<NODE_BLOCKS, 512, NODE_SMEM>>>(na, node_emb, expb, emb_cat,
                                                 projb, db1, db2);

    conv_kernel<0><<<L1 / 128, 256, CONV_SMEM>>>((const int*)d_in[i_src[0]],
        cb1 + 0 * 128, cb2 + 0 * 128, (float*)d_out);
    conv_kernel<1><<<L2 / 128, 256, CONV_SMEM>>>((const int*)d_in[i_src[1]],
        cb1 + 1 * 128, cb2 + 1 * 128, (float*)d_out);
    conv_kernel<2><<<L3 / 128, 256, CONV_SMEM>>>((const int*)d_in[i_src[2]],
        cb1 + 2 * 128, cb2 + 2 * 128, (float*)d_out);
}